// round 1
// baseline (speedup 1.0000x reference)
#include <cuda_runtime.h>
#include <cuda_bf16.h>

#define Hh 64
#define Uu 64
#define Nn 4096
#define NSWEEPS 10
#define FPITERS 3

// ---------------- scratch (device globals; no allocation allowed) ----------------
__device__ __align__(16) float g_qf[Nn];
__device__ __align__(16) float g_StS[Hh*Uu];
__device__ __align__(16) float g_Binv[64*64*64];   // 1 MB: per-h inverse of B_h
__device__ __align__(16) float g_b[Nn];
__device__ __align__(16) float g_x[Nn];
__device__ __align__(16) float g_y[Nn];
__device__ __align__(16) float g_X[Nn];            // X = x + th_P
__device__ __align__(16) float g_C[Nn];            // C = X^T X
__device__ int g_maskMode;                         // 0=u8, 1=f32, 2=i32

// ---------------- mask dtype detection ----------------
// Reads only the first 4096 BYTES (always safe: element count is 4096, >=1 B each).
// u8 mask: bytes in {0,1}, some '1' at i%4!=0.    (mode 0)
// f32 mask: 1.0f has bytes 0x80,0x3F -> badU8.    (mode 1)
// i32 mask: bytes in {0,1} but '1' only at i%4==0 (mode 2)
__global__ void k_detect(const unsigned char* __restrict__ m) {
    __shared__ int badU8, off1;
    int t = threadIdx.x;
    if (t == 0) { badU8 = 0; off1 = 0; }
    __syncthreads();
    int b1 = 0, b2 = 0;
    for (int i = t; i < 4096; i += blockDim.x) {
        unsigned v = m[i];
        if (v > 1u) b1 = 1;
        if (v == 1u && (i & 3) != 0) b2 = 1;
    }
    if (b1) badU8 = 1;
    if (b2) off1 = 1;
    __syncthreads();
    if (t == 0) g_maskMode = badU8 ? 1 : (off1 ? 0 : 2);
}

__global__ void k_qf(const void* __restrict__ m) {
    int i = blockIdx.x * blockDim.x + threadIdx.x;
    if (i >= Nn) return;
    int mode = g_maskMode;
    bool on;
    if (mode == 0)      on = ((const unsigned char*)m)[i] != 0;
    else if (mode == 1) on = ((const float*)m)[i] != 0.0f;
    else                on = ((const int*)m)[i] != 0;
    g_qf[i] = on ? 1.0f : 0.0f;
}

// ---------------- StS = S^T S ----------------
__global__ void k_sts(const float* __restrict__ S) {
    int i = blockIdx.x * blockDim.x + threadIdx.x;   // 4096
    int a = i >> 6, b = i & 63;
    float acc = 0.0f;
    #pragma unroll 8
    for (int h = 0; h < 64; h++) acc += S[h*64 + a] * S[h*64 + b];
    g_StS[i] = acc;
}

// ---------------- per-h block inverse: B_h = rho I + lam2 StS + diag(q_h) ----------------
// Gauss-Jordan on augmented [B | I], 64 rows x 130 cols (128 used), 256 threads.
// B is SPD with diag >= rho => pivots positive, no pivoting needed.
__global__ void k_binv(const float* __restrict__ lam2p, const float* __restrict__ rhop) {
    __shared__ float Aug[64*130];
    int h = blockIdx.x, t = threadIdx.x;
    int row = t >> 2, seg = t & 3;
    float lam2 = *lam2p, rho = *rhop;

    for (int idx = t; idx < 64*64; idx += 256) {
        int i = idx >> 6, j = idx & 63;
        float v = lam2 * g_StS[idx];
        if (i == j) v += rho + g_qf[h*64 + i];
        Aug[i*130 + j]      = v;
        Aug[i*130 + 64 + j] = (i == j) ? 1.0f : 0.0f;
    }
    __syncthreads();

    for (int k = 0; k < 64; k++) {
        float pinv = 1.0f / Aug[k*130 + k];
        __syncthreads();
        if (row == k) {
            #pragma unroll 8
            for (int j = seg*32; j < seg*32 + 32; j++) Aug[k*130 + j] *= pinv;
        }
        __syncthreads();
        float f = Aug[row*130 + k];
        __syncthreads();
        if (row != k) {
            #pragma unroll 8
            for (int j = seg*32; j < seg*32 + 32; j++)
                Aug[row*130 + j] -= f * Aug[k*130 + j];
        }
        __syncthreads();
    }

    for (int idx = t; idx < 4096; idx += 256) {
        int i = idx >> 6, j = idx & 63;
        g_Binv[h*4096 + idx] = Aug[i*130 + 64 + j];   // inverse is symmetric (SPD)
    }
}

// ---------------- b = rho*(L - th_P) + mask*inp ----------------
__global__ void k_b(const float* __restrict__ L, const float* __restrict__ thP,
                    const float* __restrict__ inp, const float* __restrict__ rhop) {
    int i = blockIdx.x * blockDim.x + threadIdx.x;
    if (i >= Nn) return;
    float rho = *rhop;
    g_b[i] = rho * (L[i] - thP[i]) + ((g_qf[i] != 0.0f) ? inp[i] : 0.0f);
}

// ---------------- x_h = Binv_h @ (b_h - lam1*y_h) ----------------
__global__ void k_apply(const float* __restrict__ lam1p, int useY) {
    __shared__ float zs[64];
    int h = blockIdx.x, j = threadIdx.x;
    float z = g_b[h*64 + j];
    if (useY) z -= (*lam1p) * g_y[h*64 + j];
    zs[j] = z;
    __syncthreads();
    const float* Bi = &g_Binv[h*4096];
    float acc = 0.0f;
    #pragma unroll 8
    for (int k = 0; k < 64; k++) acc += Bi[k*64 + j] * zs[k];   // symmetric -> coalesced
    g_x[h*64 + j] = acc;
}

// ---------------- y = D @ x (4096x4096 dense matvec, memory bound) ----------------
__global__ void __launch_bounds__(512) k_matvec(const float* __restrict__ D) {
    __shared__ __align__(16) float xs[4096];
    int t = threadIdx.x;
    const float4* x4 = (const float4*)g_x;
    float4* xs4 = (float4*)xs;
    for (int i = t; i < 1024; i += 512) xs4[i] = x4[i];
    __syncthreads();
    int w = t >> 5, lane = t & 31;
    int row0 = blockIdx.x * 32 + w * 2;
    for (int rr = 0; rr < 2; rr++) {
        int row = row0 + rr;
        const float4* D4 = (const float4*)(D + (size_t)row * 4096);
        float acc = 0.0f;
        #pragma unroll
        for (int it = 0; it < 32; it++) {
            float4 d = D4[lane + 32*it];
            float4 xv = xs4[lane + 32*it];
            acc += d.x*xv.x + d.y*xv.y + d.z*xv.z + d.w*xv.w;
        }
        #pragma unroll
        for (int off = 16; off > 0; off >>= 1)
            acc += __shfl_xor_sync(0xffffffffu, acc, off);
        if (lane == 0) g_y[row] = acc;
    }
}

// ---------------- X = x + th_P ; C = X^T X ----------------
__global__ void k_prep(const float* __restrict__ thP) {
    int i = blockIdx.x * blockDim.x + threadIdx.x;
    if (i < Nn) g_X[i] = g_x[i] + thP[i];
}
__global__ void k_C() {
    int i = blockIdx.x * blockDim.x + threadIdx.x;   // 4096
    int a = i >> 6, b = i & 63;
    float acc = 0.0f;
    #pragma unroll 8
    for (int h = 0; h < 64; h++) acc += g_X[h*64 + a] * g_X[h*64 + b];
    g_C[i] = acc;
}

// ---------------- SVT via two-sided Jacobi eig of C, then Ltmp/Ptmp ----------------
// One block, 1024 threads = 32 warps. Tournament ordering: warp w owns pair (p,q);
// all 32 pairs per round are disjoint. Rotation params read straight from C.
__global__ void __launch_bounds__(1024) k_final(const float* __restrict__ thP,
                                                const float* __restrict__ vp,
                                                const float* __restrict__ netap,
                                                float* __restrict__ out) {
    __shared__ float Cs[64*65];
    __shared__ float Vs[64*65];
    __shared__ float sarr[64];
    __shared__ float fscale[64];
    __shared__ float smaxsh;
    int t = threadIdx.x, w = t >> 5, lane = t & 31;

    for (int i = t; i < 4096; i += 1024) {
        int r = i >> 6, c = i & 63;
        Cs[r*65 + c] = g_C[i];
        Vs[r*65 + c] = (r == c) ? 1.0f : 0.0f;
    }
    __syncthreads();

    for (int sweep = 0; sweep < NSWEEPS; sweep++) {
        for (int r = 0; r < 63; r++) {
            int p, q;
            if (w == 0) { p = 63; q = r; }
            else { p = (r + w) % 63; q = (r + 63 - w) % 63; }

            float cpp = Cs[p*65 + p], cqq = Cs[q*65 + q], cpq = Cs[p*65 + q];
            float c = 1.0f, s = 0.0f;
            bool rot = fabsf(cpq) > 1e-30f;
            if (rot) {
                float zeta = (cqq - cpp) / (2.0f * cpq);
                float tt = 1.0f / (fabsf(zeta) + sqrtf(1.0f + zeta*zeta));
                tt = copysignf(tt, zeta);
                c = rsqrtf(1.0f + tt*tt);
                s = tt * c;
                // column phase: C <- C J, V <- V J  (own columns only)
                int r0 = lane, r1 = lane + 32;
                float ap0 = Cs[r0*65 + p], aq0 = Cs[r0*65 + q];
                float ap1 = Cs[r1*65 + p], aq1 = Cs[r1*65 + q];
                Cs[r0*65 + p] = c*ap0 - s*aq0;  Cs[r0*65 + q] = s*ap0 + c*aq0;
                Cs[r1*65 + p] = c*ap1 - s*aq1;  Cs[r1*65 + q] = s*ap1 + c*aq1;
                float vp0 = Vs[r0*65 + p], vq0 = Vs[r0*65 + q];
                float vp1 = Vs[r1*65 + p], vq1 = Vs[r1*65 + q];
                Vs[r0*65 + p] = c*vp0 - s*vq0;  Vs[r0*65 + q] = s*vp0 + c*vq0;
                Vs[r1*65 + p] = c*vp1 - s*vq1;  Vs[r1*65 + q] = s*vp1 + c*vq1;
            }
            __syncthreads();
            if (rot) {
                // row phase: C <- J^T C  (own rows only)
                int c0 = lane, c1 = lane + 32;
                float ap0 = Cs[p*65 + c0], aq0 = Cs[q*65 + c0];
                float ap1 = Cs[p*65 + c1], aq1 = Cs[q*65 + c1];
                Cs[p*65 + c0] = c*ap0 - s*aq0;  Cs[q*65 + c0] = s*ap0 + c*aq0;
                Cs[p*65 + c1] = c*ap1 - s*aq1;  Cs[q*65 + c1] = s*ap1 + c*aq1;
            }
            __syncthreads();
        }
    }

    // singular values + threshold factors
    if (t < 64) sarr[t] = sqrtf(fmaxf(Cs[t*65 + t], 0.0f));
    __syncthreads();
    if (t == 0) {
        float m = 0.0f;
        for (int j = 0; j < 64; j++) m = fmaxf(m, sarr[j]);
        smaxsh = m;
    }
    __syncthreads();
    if (t < 64) {
        float vv  = *vp;
        float tau = 0.4f / (1.0f + expf(-vv));
        float thr = tau * smaxsh;
        float sj  = sarr[t];
        fscale[t] = (sj > thr) ? (sj - thr) / sj : 0.0f;
    }
    __syncthreads();

    // W' = (X V) * diag(f), reusing Cs as storage
    for (int i = t; i < 4096; i += 1024) {
        int h = i >> 6, j = i & 63;
        float acc = 0.0f;
        #pragma unroll 8
        for (int u = 0; u < 64; u++) acc += g_X[h*64 + u] * Vs[u*65 + j];
        Cs[h*65 + j] = acc * fscale[j];
    }
    __syncthreads();

    // Ltmp = W' V^T ; Ptmp = th_P + neta*(x - Ltmp)
    float neta = *netap;
    for (int i = t; i < 4096; i += 1024) {
        int h = i >> 6, k = i & 63;
        float acc = 0.0f;
        #pragma unroll 8
        for (int j = 0; j < 64; j++) acc += Cs[h*65 + j] * Vs[k*65 + j];
        out[i]        = acc;
        out[4096 + i] = thP[i] + neta * (g_x[i] - acc);
    }
}

// ---------------- launch ----------------
extern "C" void kernel_launch(void* const* d_in, const int* in_sizes, int n_in,
                              void* d_out, int out_size) {
    const float* inp  = (const float*)d_in[0];
    const float* L    = (const float*)d_in[1];
    const void*  mask = d_in[2];
    const float* D    = (const float*)d_in[3];
    const float* thP  = (const float*)d_in[4];
    const float* v    = (const float*)d_in[5];
    const float* neta = (const float*)d_in[6];
    const float* lam1 = (const float*)d_in[7];
    const float* lam2 = (const float*)d_in[8];
    const float* rho  = (const float*)d_in[9];
    const float* S    = (const float*)d_in[10];
    float* out = (float*)d_out;

    k_detect<<<1, 256>>>((const unsigned char*)mask);
    k_qf    <<<16, 256>>>(mask);
    k_sts   <<<16, 256>>>(S);
    k_binv  <<<64, 256>>>(lam2, rho);
    k_b     <<<16, 256>>>(L, thP, inp, rho);
    k_apply <<<64, 64>>>(lam1, 0);                 // x0 = A0^{-1} b
    for (int it = 0; it < FPITERS; it++) {
        k_matvec<<<128, 512>>>(D);                 // y = D x
        k_apply <<<64, 64>>>(lam1, 1);             // x = A0^{-1}(b - lam1 y)
    }
    k_prep  <<<16, 256>>>(thP);
    k_C     <<<16, 256>>>();
    k_final <<<1, 1024>>>(thP, v, neta, out);
}

// round 2
// speedup vs baseline: 1.7041x; 1.7041x over previous
#include <cuda_runtime.h>
#include <cuda_bf16.h>

#define Nn 4096
#define FPITERS 3
#define NIN 12          // inner Jacobi iterations for block solves
#define MAXSWEEP 10     // one-sided Jacobi SVD max sweeps (early exit)
#define HPB 4           // h-blocks per CTA in k_apply

// ---------------- scratch (device globals; no allocation allowed) ----------------
__device__ __align__(16) float g_qf[Nn];
__device__ __align__(16) float g_StS[64*64];
__device__ __align__(16) float g_b[Nn];
__device__ __align__(16) float g_x[Nn];
__device__ __align__(16) float g_y[Nn];

// ---------------- prep: mask detect + qf + b (block 0), StS (blocks 1..4) --------
// Mask dtype detection reads only first 4096 BYTES (>=1 B per element, safe).
__global__ void __launch_bounds__(1024) k_prep(const void* __restrict__ mask,
                                               const float* __restrict__ S,
                                               const float* __restrict__ L,
                                               const float* __restrict__ thP,
                                               const float* __restrict__ inp,
                                               const float* __restrict__ rhop) {
    int t = threadIdx.x;
    if (blockIdx.x == 0) {
        __shared__ int badU8, off1;
        if (t == 0) { badU8 = 0; off1 = 0; }
        __syncthreads();
        const unsigned char* m8 = (const unsigned char*)mask;
        int b1 = 0, b2 = 0;
        for (int i = t; i < 4096; i += 1024) {
            unsigned v = m8[i];
            if (v > 1u) b1 = 1;
            if (v == 1u && (i & 3) != 0) b2 = 1;
        }
        if (b1) badU8 = 1;       // benign races: all write 1
        if (b2) off1 = 1;
        __syncthreads();
        int mode = badU8 ? 1 : (off1 ? 0 : 2);   // 0=u8, 1=f32, 2=i32
        float rho = *rhop;
        for (int i = t; i < 4096; i += 1024) {
            bool on;
            if (mode == 0)      on = ((const unsigned char*)mask)[i] != 0;
            else if (mode == 1) on = ((const float*)mask)[i] != 0.0f;
            else                on = ((const int*)mask)[i] != 0;
            g_qf[i] = on ? 1.0f : 0.0f;
            g_b[i]  = rho * (L[i] - thP[i]) + (on ? inp[i] : 0.0f);
        }
    } else {
        __shared__ float Ss[64*65];
        for (int i = t; i < 4096; i += 1024) { int h = i >> 6, a = i & 63; Ss[h*65 + a] = S[i]; }
        __syncthreads();
        int idx = (blockIdx.x - 1) * 1024 + t;
        int a = idx >> 6, b = idx & 63;
        float acc = 0.0f;
        #pragma unroll
        for (int h = 0; h < 64; h++) acc += Ss[h*65 + a] * Ss[h*65 + b];
        g_StS[idx] = acc;
    }
}

// ---------------- apply: x_h = B_h^{-1} r_h via diagonal-preconditioned Jacobi ----
// B_h = rho I + lam2*StS + diag(q_h); off-diag contraction ~0.3 -> NIN iters ample.
__global__ void __launch_bounds__(256) k_apply(const float* __restrict__ lam1p,
                                               const float* __restrict__ lam2p,
                                               const float* __restrict__ rhop,
                                               int useY) {
    __shared__ float Ms[64*65];
    __shared__ float zs[HPB][64];
    int t = threadIdx.x;
    int g = t >> 6, u = t & 63;
    int h = blockIdx.x * HPB + g;
    for (int i = t; i < 4096; i += 256) { int a = i >> 6, c = i & 63; Ms[a*65 + c] = g_StS[i]; }
    float lam2 = *lam2p, rho = *rhop;
    float r = g_b[h*64 + u];
    if (useY) r -= (*lam1p) * g_y[h*64 + u];
    __syncthreads();
    float Muu  = Ms[u*65 + u];
    float dinv = 1.0f / (rho + g_qf[h*64 + u] + lam2 * Muu);
    float z = useY ? g_x[h*64 + u] : r * dinv;    // warm start on later applies
    for (int it = 0; it < NIN; it++) {
        zs[g][u] = z;
        __syncthreads();
        float acc = 0.0f;
        #pragma unroll
        for (int c = 0; c < 64; c++) acc += Ms[u*65 + c] * zs[g][c];
        z = (r - lam2 * (acc - Muu * z)) * dinv;
        __syncthreads();
    }
    g_x[h*64 + u] = z;
}

// ---------------- y = D @ x (4096x4096 dense matvec, L2/HBM bound) ----------------
__global__ void __launch_bounds__(512) k_matvec(const float* __restrict__ D) {
    __shared__ __align__(16) float xs[4096];
    int t = threadIdx.x;
    const float4* x4 = (const float4*)g_x;
    float4* xs4 = (float4*)xs;
    for (int i = t; i < 1024; i += 512) xs4[i] = x4[i];
    __syncthreads();
    int w = t >> 5, lane = t & 31;
    int row0 = blockIdx.x * 32 + w * 2;
    for (int rr = 0; rr < 2; rr++) {
        int row = row0 + rr;
        const float4* D4 = (const float4*)(D + (size_t)row * 4096);
        float acc = 0.0f;
        #pragma unroll
        for (int it = 0; it < 32; it++) {
            float4 d  = D4[lane + 32*it];
            float4 xv = xs4[lane + 32*it];
            acc += d.x*xv.x + d.y*xv.y + d.z*xv.z + d.w*xv.w;
        }
        #pragma unroll
        for (int off = 16; off > 0; off >>= 1)
            acc += __shfl_xor_sync(0xffffffffu, acc, off);
        if (lane == 0) g_y[row] = acc;
    }
}

// ---------------- one-sided Jacobi SVD of X = x + thP, then SVT + outputs --------
// G starts as X; rotations orthogonalize columns: G -> X*V = U*diag(s).
// Ltmp = G diag(s_thr/s^3) G^T X  (no V needed). Norms maintained incrementally.
__global__ void __launch_bounds__(1024) k_final(const float* __restrict__ thP,
                                                const float* __restrict__ vp,
                                                const float* __restrict__ netap,
                                                float* __restrict__ out) {
    __shared__ float Gs[64*65];   // column-major: Gs[col*65 + row]
    __shared__ float Xs[64*65];   // pristine X (later reused for W)
    __shared__ float nrm[64];     // running squared column norms
    __shared__ float sarr[64];
    __shared__ float fsc[64];
    __shared__ float thr_s;
    __shared__ int rotflag;
    int t = threadIdx.x, w = t >> 5, lane = t & 31;

    for (int i = t; i < 4096; i += 1024) {
        int r = i >> 6, j = i & 63;
        float xv = g_x[i] + thP[i];
        Gs[j*65 + r] = xv;
        Xs[j*65 + r] = xv;
    }
    if (t == 0) rotflag = 0;
    __syncthreads();
    if (t < 64) {
        float acc = 0.0f;
        #pragma unroll
        for (int r = 0; r < 64; r++) { float g = Gs[t*65 + r]; acc += g*g; }
        nrm[t] = acc;
    }
    __syncthreads();

    for (int sweep = 0; sweep < MAXSWEEP; sweep++) {
        for (int r = 0; r < 63; r++) {
            int p, q;
            if (w == 0) { p = 63; q = r; }
            else { p = (r + w) % 63; q = (r + 63 - w) % 63; }

            float ap0 = Gs[p*65 + lane], ap1 = Gs[p*65 + lane + 32];
            float aq0 = Gs[q*65 + lane], aq1 = Gs[q*65 + lane + 32];
            float dpq = ap0*aq0 + ap1*aq1;
            #pragma unroll
            for (int o = 16; o; o >>= 1) dpq += __shfl_xor_sync(0xffffffffu, dpq, o);
            float npp = nrm[p], nqq = nrm[q];
            if (dpq*dpq > 1e-11f * npp * nqq) {
                float zeta = (nqq - npp) / (2.0f * dpq);
                float tt = copysignf(1.0f / (fabsf(zeta) + sqrtf(1.0f + zeta*zeta)), zeta);
                float c = rsqrtf(1.0f + tt*tt), s = tt * c;
                Gs[p*65 + lane]      = c*ap0 - s*aq0;
                Gs[q*65 + lane]      = s*ap0 + c*aq0;
                Gs[p*65 + lane + 32] = c*ap1 - s*aq1;
                Gs[q*65 + lane + 32] = s*ap1 + c*aq1;
                if (lane == 0) {
                    nrm[p] = npp - tt * dpq;
                    nrm[q] = nqq + tt * dpq;
                    rotflag = 1;
                }
            }
            __syncthreads();
        }
        int done = (rotflag == 0);
        __syncthreads();
        if (t == 0) rotflag = 0;
        __syncthreads();
        if (done) break;
    }

    // fresh singular values + threshold factors
    if (t < 64) {
        float acc = 0.0f;
        #pragma unroll
        for (int r = 0; r < 64; r++) { float g = Gs[t*65 + r]; acc += g*g; }
        sarr[t] = sqrtf(acc);
    }
    __syncthreads();
    if (t == 0) {
        float m = 0.0f;
        for (int j = 0; j < 64; j++) m = fmaxf(m, sarr[j]);
        float vv = *vp;
        float tau = 0.4f / (1.0f + expf(-vv));
        thr_s = tau * m;
    }
    __syncthreads();
    if (t < 64) {
        float s = sarr[t];
        float st = s - thr_s;
        fsc[t] = (st > 0.0f) ? st / (s*s*s) : 0.0f;
    }
    __syncthreads();

    // W[j][c] = fsc[j] * sum_r G[r,j] X[r,c]   (into registers)
    float wreg[4];
    #pragma unroll
    for (int k = 0; k < 4; k++) {
        int idx = t + k*1024;
        int jj = idx >> 6, c = idx & 63;
        float acc = 0.0f;
        #pragma unroll
        for (int r = 0; r < 64; r++) acc += Gs[jj*65 + r] * Xs[c*65 + r];
        wreg[k] = acc * fsc[jj];
    }
    __syncthreads();
    // store W into Xs (reuse), layout Xs[c*65 + j] for conflict-free column reads
    #pragma unroll
    for (int k = 0; k < 4; k++) {
        int idx = t + k*1024;
        int jj = idx >> 6, c = idx & 63;
        Xs[c*65 + jj] = wreg[k];
    }
    __syncthreads();

    // Ltmp[r,c] = sum_j G[r,j] W[j,c] ; Ptmp = thP + neta*(x - Ltmp)
    float neta = *netap;
    for (int i = t; i < 4096; i += 1024) {
        int r = i >> 6, c = i & 63;
        float acc = 0.0f;
        #pragma unroll
        for (int j = 0; j < 64; j++) acc += Gs[j*65 + r] * Xs[c*65 + j];
        out[i]        = acc;
        out[4096 + i] = thP[i] + neta * (g_x[i] - acc);
    }
}

// ---------------- launch ----------------
extern "C" void kernel_launch(void* const* d_in, const int* in_sizes, int n_in,
                              void* d_out, int out_size) {
    const float* inp  = (const float*)d_in[0];
    const float* L    = (const float*)d_in[1];
    const void*  mask = d_in[2];
    const float* D    = (const float*)d_in[3];
    const float* thP  = (const float*)d_in[4];
    const float* v    = (const float*)d_in[5];
    const float* neta = (const float*)d_in[6];
    const float* lam1 = (const float*)d_in[7];
    const float* lam2 = (const float*)d_in[8];
    const float* rho  = (const float*)d_in[9];
    const float* S    = (const float*)d_in[10];
    float* out = (float*)d_out;

    k_prep <<<5, 1024>>>(mask, S, L, thP, inp, rho);
    k_apply<<<64/HPB, 256>>>(lam1, lam2, rho, 0);          // x0 = A0^{-1} b
    for (int it = 0; it < FPITERS; it++) {
        k_matvec<<<128, 512>>>(D);                          // y = D x
        k_apply<<<64/HPB, 256>>>(lam1, lam2, rho, 1);       // x = A0^{-1}(b - lam1 y)
    }
    k_final<<<1, 1024>>>(thP, v, neta, out);
}

// round 3
// speedup vs baseline: 1.8765x; 1.1012x over previous
#include <cuda_runtime.h>
#include <cuda_bf16.h>

#define NCTA 128
#define TPB  512
#define FPITERS 2
#define NIN0 14
#define NIN1 8
#define MAXSWEEP 8

// ---------------- device scratch (no allocation allowed) ----------------
__device__ __align__(16) float g_qf[4096];
__device__ __align__(16) float g_StS[4096];
__device__ __align__(16) float g_b[4096];
__device__ __align__(16) float g_x[4096];
__device__ __align__(16) float g_y[4096];
__device__ int g_cnt = 0;
__device__ int g_gen = 0;   // monotone across graph replays; g_cnt self-resets

// device-wide barrier: safe across replays (count returns to 0 at each release,
// gen only ever increments; spinners wait on gen, so count reset can't be lost)
__device__ __forceinline__ void gbar() {
    __threadfence();
    __syncthreads();
    if (threadIdx.x == 0) {
        int my = *(volatile int*)&g_gen;
        int old = atomicAdd(&g_cnt, 1);
        if (old == NCTA - 1) {
            g_cnt = 0;
            __threadfence();
            atomicAdd(&g_gen, 1);
        } else {
            while (*(volatile int*)&g_gen == my) __nanosleep(32);
        }
    }
    __syncthreads();
    __threadfence();
}

struct SolveSm {
    float Ms[64*65];      // StS (apply); Ss staging (prep)
    float xs[4096];       // matvec x cache
    float zs[2][64];      // apply double buffer
};
struct FinalSm {
    float Gs[64*65];
    float Xs[64*65];
    float nrm[64];
    float sarr[64];
    float fsc[64];
    float thr_s;
};
union Smem { SolveSm s; FinalSm f; };

__global__ void __launch_bounds__(TPB, 1)
k_all(const float* __restrict__ inp, const float* __restrict__ L,
      const void* __restrict__ mask, const float* __restrict__ D,
      const float* __restrict__ thP, const float* __restrict__ vp,
      const float* __restrict__ netap, const float* __restrict__ lam1p,
      const float* __restrict__ lam2p, const float* __restrict__ rhop,
      const float* __restrict__ S, float* __restrict__ out) {
    __shared__ Smem sm;
    __shared__ int s_badU8, s_off1;
    int t = threadIdx.x;
    int cta = blockIdx.x;

    // ================= phase 0: prep =================
    if (cta == 0) {
        // mask dtype detect on first 4096 bytes (>=1B/elem, safe)
        if (t == 0) { s_badU8 = 0; s_off1 = 0; }
        __syncthreads();
        const unsigned char* m8 = (const unsigned char*)mask;
        int b1 = 0, b2 = 0;
        for (int i = t; i < 4096; i += TPB) {
            unsigned v = m8[i];
            if (v > 1u) b1 = 1;
            if (v == 1u && (i & 3) != 0) b2 = 1;
        }
        if (b1) s_badU8 = 1;        // benign races
        if (b2) s_off1 = 1;
        __syncthreads();
        int mode = s_badU8 ? 1 : (s_off1 ? 0 : 2);   // 0=u8,1=f32,2=i32
        float rho = *rhop;
        for (int i = t; i < 4096; i += TPB) {
            bool on;
            if (mode == 0)      on = ((const unsigned char*)mask)[i] != 0;
            else if (mode == 1) on = ((const float*)mask)[i] != 0.0f;
            else                on = ((const int*)mask)[i] != 0;
            g_qf[i] = on ? 1.0f : 0.0f;
            g_b[i]  = rho * (L[i] - thP[i]) + (on ? inp[i] : 0.0f);
        }
    } else if (cta <= 4) {
        // StS = S^T S, quadrant per CTA
        for (int i = t; i < 4096; i += TPB) { int h = i >> 6, a = i & 63; sm.s.Ms[h*65 + a] = S[i]; }
        __syncthreads();
        int base = (cta - 1) * 1024;
        #pragma unroll
        for (int k = 0; k < 2; k++) {
            int idx = base + t + k*TPB;
            int a = idx >> 6, b = idx & 63;
            float acc = 0.0f;
            #pragma unroll 16
            for (int h = 0; h < 64; h++) acc += sm.s.Ms[h*65 + a] * sm.s.Ms[h*65 + b];
            g_StS[idx] = acc;
        }
    }
    gbar();   // 1

    float lam1 = *lam1p, lam2 = *lam2p, rho = *rhop;

    // apply CTAs (0..63) stage StS into smem once; persists across phases
    if (cta < 64) {
        for (int i = t; i < 4096; i += TPB) { int a = i >> 6, c = i & 63; sm.s.Ms[a*65 + c] = g_StS[i]; }
        __syncthreads();
    }

    // ---------------- apply lambda (64 threads/CTA, named barrier) --------
    auto apply = [&](int useY, int nin) {
        if (cta < 64 && t < 64) {
            int h = cta, u = t;
            float r = g_b[h*64 + u];
            if (useY) r -= lam1 * g_y[h*64 + u];
            float Muu  = sm.s.Ms[u*65 + u];
            float dinv = 1.0f / (rho + g_qf[h*64 + u] + lam2 * Muu);
            float z = useY ? g_x[h*64 + u] : r * dinv;
            int cur = 0;
            sm.s.zs[0][u] = z;
            asm volatile("bar.sync 1, 64;" ::: "memory");
            for (int it = 0; it < nin; it++) {
                float a0=0.f,a1=0.f,a2=0.f,a3=0.f;
                const float* Mr = &sm.s.Ms[u*65];
                const float* zc = sm.s.zs[cur];
                #pragma unroll 16
                for (int c = 0; c < 64; c += 4) {
                    a0 += Mr[c]   * zc[c];
                    a1 += Mr[c+1] * zc[c+1];
                    a2 += Mr[c+2] * zc[c+2];
                    a3 += Mr[c+3] * zc[c+3];
                }
                float acc = (a0+a1) + (a2+a3);
                z = (r - lam2 * (acc - Muu * z)) * dinv;
                if (it + 1 < nin) {
                    sm.s.zs[cur^1][u] = z;
                    asm volatile("bar.sync 1, 64;" ::: "memory");
                    cur ^= 1;
                }
            }
            g_x[h*64 + u] = z;
        }
    };

    // ---------------- matvec lambda: y = D x (all 128 CTAs) --------------
    auto matvec = [&]() {
        const float4* x4 = (const float4*)g_x;
        float4* xs4 = (float4*)sm.s.xs;
        for (int i = t; i < 1024; i += TPB) xs4[i] = x4[i];
        __syncthreads();
        int w = t >> 5, lane = t & 31;
        int row0 = cta * 32 + w * 2;
        #pragma unroll
        for (int rr = 0; rr < 2; rr++) {
            int row = row0 + rr;
            const float4* D4 = (const float4*)(D + (size_t)row * 4096);
            float acc = 0.0f;
            #pragma unroll
            for (int it = 0; it < 32; it++) {
                float4 d  = D4[lane + 32*it];
                float4 xv = xs4[lane + 32*it];
                acc += d.x*xv.x + d.y*xv.y + d.z*xv.z + d.w*xv.w;
            }
            #pragma unroll
            for (int off = 16; off > 0; off >>= 1)
                acc += __shfl_xor_sync(0xffffffffu, acc, off);
            if (lane == 0) g_y[row] = acc;
        }
        __syncthreads();   // xs reused next phase
    };

    apply(0, NIN0);
    gbar();   // 2
    for (int it = 0; it < FPITERS; it++) {
        matvec();
        gbar();           // 3, 5
        apply(1, NIN1);
        gbar();           // 4, 6
    }

    if (cta != 0) return;

    // ================= final: one-sided Jacobi SVD + SVT (CTA0) ==========
    float* Gs = sm.f.Gs;
    float* Xs = sm.f.Xs;
    float* nrm = sm.f.nrm;
    int w = t >> 5, lane = t & 31;

    for (int i = t; i < 4096; i += TPB) {
        int r = i >> 6, j = i & 63;
        float xv = g_x[i] + thP[i];
        Gs[j*65 + r] = xv;
        Xs[j*65 + r] = xv;
    }
    __syncthreads();
    if (t < 64) {
        float acc = 0.0f;
        #pragma unroll 16
        for (int r = 0; r < 64; r++) { float g = Gs[t*65 + r]; acc += g*g; }
        nrm[t] = acc;
    }
    __syncthreads();

    // warp w handles tournament pairs k0=2w, k1=2w+1; incremental p/q (no %)
    int k0 = w << 1, k1 = k0 + 1;
    for (int sweep = 0; sweep < MAXSWEEP; sweep++) {
        int did = 0;
        int p0, q0, p1, q1;
        if (k0 == 0) { p0 = 63; q0 = 0; }
        else { p0 = k0; q0 = 63 - k0; }
        p1 = k1; q1 = 63 - k1;
        for (int r = 0; r < 63; r++) {
            float a0 = Gs[p0*65 + lane], b0 = Gs[p0*65 + lane + 32];
            float c0 = Gs[q0*65 + lane], d0 = Gs[q0*65 + lane + 32];
            float a1 = Gs[p1*65 + lane], b1 = Gs[p1*65 + lane + 32];
            float c1 = Gs[q1*65 + lane], d1 = Gs[q1*65 + lane + 32];
            float dp0 = a0*c0 + b0*d0;
            float dp1 = a1*c1 + b1*d1;
            #pragma unroll
            for (int o = 16; o; o >>= 1) {
                dp0 += __shfl_xor_sync(0xffffffffu, dp0, o);
                dp1 += __shfl_xor_sync(0xffffffffu, dp1, o);
            }
            float npp0 = nrm[p0], nqq0 = nrm[q0];
            if (dp0*dp0 > 1e-9f * npp0 * nqq0) {
                float zeta = (nqq0 - npp0) / (2.0f * dp0);
                float tt = copysignf(1.0f / (fabsf(zeta) + sqrtf(1.0f + zeta*zeta)), zeta);
                float c = rsqrtf(1.0f + tt*tt), s = tt * c;
                Gs[p0*65 + lane]      = c*a0 - s*c0;
                Gs[q0*65 + lane]      = s*a0 + c*c0;
                Gs[p0*65 + lane + 32] = c*b0 - s*d0;
                Gs[q0*65 + lane + 32] = s*b0 + c*d0;
                if (lane == 0) { nrm[p0] = npp0 - tt*dp0; nrm[q0] = nqq0 + tt*dp0; }
                did = 1;
            }
            float npp1 = nrm[p1], nqq1 = nrm[q1];
            if (dp1*dp1 > 1e-9f * npp1 * nqq1) {
                float zeta = (nqq1 - npp1) / (2.0f * dp1);
                float tt = copysignf(1.0f / (fabsf(zeta) + sqrtf(1.0f + zeta*zeta)), zeta);
                float c = rsqrtf(1.0f + tt*tt), s = tt * c;
                Gs[p1*65 + lane]      = c*a1 - s*c1;
                Gs[q1*65 + lane]      = s*a1 + c*c1;
                Gs[p1*65 + lane + 32] = c*b1 - s*d1;
                Gs[q1*65 + lane + 32] = s*b1 + c*d1;
                if (lane == 0) { nrm[p1] = npp1 - tt*dp1; nrm[q1] = nqq1 + tt*dp1; }
                did = 1;
            }
            __syncthreads();
            // increment tournament indices mod 63 (p0=63 fixed for warp 0)
            if (k0 == 0) { q0 = (q0 + 1 == 63) ? 0 : q0 + 1; }
            else { p0 = (p0 + 1 == 63) ? 0 : p0 + 1; q0 = (q0 + 1 == 63) ? 0 : q0 + 1; }
            p1 = (p1 + 1 == 63) ? 0 : p1 + 1;
            q1 = (q1 + 1 == 63) ? 0 : q1 + 1;
        }
        if (!__syncthreads_or(did)) break;
    }

    // singular values + threshold
    if (t < 64) {
        float acc = 0.0f;
        #pragma unroll 16
        for (int r = 0; r < 64; r++) { float g = Gs[t*65 + r]; acc += g*g; }
        sm.f.sarr[t] = sqrtf(acc);
    }
    __syncthreads();
    if (t == 0) {
        float m = 0.0f;
        for (int j = 0; j < 64; j++) m = fmaxf(m, sm.f.sarr[j]);
        float vv = *vp;
        float tau = 0.4f / (1.0f + expf(-vv));
        sm.f.thr_s = tau * m;
    }
    __syncthreads();
    if (t < 64) {
        float s = sm.f.sarr[t];
        float st = s - sm.f.thr_s;
        sm.f.fsc[t] = (st > 0.0f) ? st / (s*s*s) : 0.0f;
    }
    __syncthreads();

    // W[j][c] = fsc[j] * sum_r G[r,j] X[r,c]
    float wreg[8];
    #pragma unroll
    for (int k = 0; k < 8; k++) {
        int idx = t + k*TPB;
        int jj = idx >> 6, c = idx & 63;
        float acc = 0.0f;
        #pragma unroll 16
        for (int r = 0; r < 64; r++) acc += Gs[jj*65 + r] * Xs[c*65 + r];
        wreg[k] = acc * sm.f.fsc[jj];
    }
    __syncthreads();
    #pragma unroll
    for (int k = 0; k < 8; k++) {
        int idx = t + k*TPB;
        int jj = idx >> 6, c = idx & 63;
        Xs[c*65 + jj] = wreg[k];   // W, transposed layout
    }
    __syncthreads();

    // Ltmp = G W ; Ptmp = thP + neta*(x - Ltmp)
    float neta = *netap;
    #pragma unroll
    for (int k = 0; k < 8; k++) {
        int i = t + k*TPB;
        int r = i >> 6, c = i & 63;
        float acc = 0.0f;
        #pragma unroll 16
        for (int j = 0; j < 64; j++) acc += Gs[j*65 + r] * Xs[c*65 + j];
        out[i]        = acc;
        out[4096 + i] = thP[i] + neta * (g_x[i] - acc);
    }
}

// ---------------- launch ----------------
extern "C" void kernel_launch(void* const* d_in, const int* in_sizes, int n_in,
                              void* d_out, int out_size) {
    const float* inp  = (const float*)d_in[0];
    const float* L    = (const float*)d_in[1];
    const void*  mask = d_in[2];
    const float* D    = (const float*)d_in[3];
    const float* thP  = (const float*)d_in[4];
    const float* v    = (const float*)d_in[5];
    const float* neta = (const float*)d_in[6];
    const float* lam1 = (const float*)d_in[7];
    const float* lam2 = (const float*)d_in[8];
    const float* rho  = (const float*)d_in[9];
    const float* S    = (const float*)d_in[10];
    float* out = (float*)d_out;

    k_all<<<NCTA, TPB>>>(inp, L, mask, D, thP, v, neta, lam1, lam2, rho, S, out);
}